// round 3
// baseline (speedup 1.0000x reference)
#include <cuda_runtime.h>

// Problem constants
#define CB 16               // batch
#define CC 64               // channels
#define CH 128
#define CW 128
#define CN (CH*CW)          // 16384 spatial positions
#define PLANE ((long)CC*CN) // elems per batch = 1048576
#define TOTE 16777216       // total elems

// -------- scratch (device globals: allocation-guard-safe) --------
__device__ float g_q[2][TOTE];
__device__ float g_k[2][TOTE];
__device__ float g_v[2][TOTE];
__device__ float g_fused[TOTE];
__device__ float g_psum[CB*CC];
__device__ float g_psumsq[CB*CC];
__device__ float g_scale[CC];
__device__ float g_shift[CC];

// ============================================================
// Projection: out[b,o,n] = sum_c W[o,c]*in[b,c,n] + bias[o]
// One thread owns one spatial column n (64-ch column in registers).
// ============================================================
__device__ __forceinline__ void proj_one(const float* __restrict__ ws,
                                         const float* __restrict__ bias,
                                         const float col[64],
                                         float* __restrict__ out, long base)
{
#pragma unroll 2
    for (int og = 0; og < 64; og += 8) {
        float acc[8];
#pragma unroll
        for (int j = 0; j < 8; j++) acc[j] = __ldg(bias + og + j);
#pragma unroll
        for (int c4 = 0; c4 < 16; c4++) {
#pragma unroll
            for (int j = 0; j < 8; j++) {
                float4 w4 = *reinterpret_cast<const float4*>(ws + (og + j) * 64 + c4 * 4);
                acc[j] = fmaf(w4.x, col[c4*4+0], acc[j]);
                acc[j] = fmaf(w4.y, col[c4*4+1], acc[j]);
                acc[j] = fmaf(w4.z, col[c4*4+2], acc[j]);
                acc[j] = fmaf(w4.w, col[c4*4+3], acc[j]);
            }
        }
#pragma unroll
        for (int j = 0; j < 8; j++) out[base + (long)(og + j) * CN] = acc[j];
    }
}

__global__ void proj_kernel(const float* __restrict__ x, const float* __restrict__ rssi,
                            const float* __restrict__ qw, const float* __restrict__ qb,
                            const float* __restrict__ kw, const float* __restrict__ kb,
                            const float* __restrict__ vw, const float* __restrict__ vb,
                            int branch)
{
    extern __shared__ float sw[];           // 3 * 4096 floats = 48KB
    float* swq = sw;
    float* swk = sw + 4096;
    float* swv = sw + 8192;
    int t = threadIdx.x;
    for (int i = t; i < 4096; i += 256) { swq[i] = qw[i]; swk[i] = kw[i]; swv[i] = vw[i]; }
    __syncthreads();

    int b = blockIdx.y;
    int n = blockIdx.x * 256 + t;
    long base = (long)b * PLANE + n;

    float col[64];

    // Q from rssi
#pragma unroll
    for (int c = 0; c < 64; c++) col[c] = rssi[base + (long)c * CN];
    proj_one(swq, qb, col, g_q[branch], base);

    // K, V from x (load column once, use twice)
#pragma unroll
    for (int c = 0; c < 64; c++) col[c] = x[base + (long)c * CN];
    proj_one(swk, kb, col, g_k[branch], base);
    proj_one(swv, vb, col, g_v[branch], base);
}

// ============================================================
// Attention per (b,c): S = Q K^T * 1/sqrt(128), softmax rows, O = S V.
// Branch 0 writes g_fused, branch 1 adds and collects BN partials.
// ============================================================
#define KP 132   // smem pitch in floats (conflict-free for row-strided float4)

__global__ void attn_kernel()
{
    extern __shared__ float sm[];
    float* Ks   = sm;                    // 128*132
    float* Vs   = sm + 128 * KP;         // 128*132
    float* rbuf = sm + 2 * 128 * KP;     // 16 warps * 128

    int t = threadIdx.x;
    int lane = t & 31;
    int warp = t >> 5;
    int bc = blockIdx.x;                 // b*64 + c
    long base = (long)bc * CN;           // == b*PLANE + c*CN

    const float sc = 0.088388347648318447f;  // 1/sqrt(128)
    float lsum = 0.f, lsq = 0.f;

    for (int br = 0; br < 2; br++) {
        const float* Qp = g_q[br] + base;
        const float* Kp = g_k[br] + base;
        const float* Vp = g_v[br] + base;

        __syncthreads();   // protect smem reuse across branches
        for (int i = t; i < 128 * 32; i += 512) {
            int g = i >> 5, wv = i & 31;
            float4 kk = reinterpret_cast<const float4*>(Kp + g * CW)[wv];
            float4 vv = reinterpret_cast<const float4*>(Vp + g * CW)[wv];
            reinterpret_cast<float4*>(Ks + g * KP)[wv] = kk;
            reinterpret_cast<float4*>(Vs + g * KP)[wv] = vv;
        }
        __syncthreads();

        float* rw = rbuf + warp * 128;
        for (int h = warp; h < 128; h += 16) {
            // stage q row in smem for broadcast
            float4 qv = reinterpret_cast<const float4*>(Qp + (long)h * CW)[lane];
            __syncwarp();
            reinterpret_cast<float4*>(rw)[lane] = qv;
            __syncwarp();

            // phase 1: scores for g = lane, lane+32, lane+64, lane+96
            float a0 = 0.f, a1 = 0.f, a2 = 0.f, a3 = 0.f;
#pragma unroll 4
            for (int wv = 0; wv < 32; wv++) {
                float4 q4 = reinterpret_cast<const float4*>(rw)[wv];
                float4 k0 = reinterpret_cast<const float4*>(Ks + (lane      ) * KP)[wv];
                float4 k1 = reinterpret_cast<const float4*>(Ks + (lane + 32 ) * KP)[wv];
                float4 k2 = reinterpret_cast<const float4*>(Ks + (lane + 64 ) * KP)[wv];
                float4 k3 = reinterpret_cast<const float4*>(Ks + (lane + 96 ) * KP)[wv];
                a0 = fmaf(q4.x,k0.x, fmaf(q4.y,k0.y, fmaf(q4.z,k0.z, fmaf(q4.w,k0.w, a0))));
                a1 = fmaf(q4.x,k1.x, fmaf(q4.y,k1.y, fmaf(q4.z,k1.z, fmaf(q4.w,k1.w, a1))));
                a2 = fmaf(q4.x,k2.x, fmaf(q4.y,k2.y, fmaf(q4.z,k2.z, fmaf(q4.w,k2.w, a2))));
                a3 = fmaf(q4.x,k3.x, fmaf(q4.y,k3.y, fmaf(q4.z,k3.z, fmaf(q4.w,k3.w, a3))));
            }

            // softmax over 128 (4 per lane), scale folded into exp
            float m = fmaxf(fmaxf(a0, a1), fmaxf(a2, a3));
            for (int o = 16; o; o >>= 1) m = fmaxf(m, __shfl_xor_sync(0xffffffffu, m, o));
            float p0 = __expf((a0 - m) * sc);
            float p1 = __expf((a1 - m) * sc);
            float p2 = __expf((a2 - m) * sc);
            float p3 = __expf((a3 - m) * sc);
            float s = p0 + p1 + p2 + p3;
            for (int o = 16; o; o >>= 1) s += __shfl_xor_sync(0xffffffffu, s, o);
            float inv = 1.f / s;

            __syncwarp();
            rw[lane     ] = p0 * inv;
            rw[lane + 32] = p1 * inv;
            rw[lane + 64] = p2 * inv;
            rw[lane + 96] = p3 * inv;
            __syncwarp();

            // phase 2: O row (lane owns 4 consecutive w)
            float4 oa = make_float4(0.f, 0.f, 0.f, 0.f);
#pragma unroll 4
            for (int g = 0; g < 128; g++) {
                float pg = rw[g];
                float4 v4 = reinterpret_cast<const float4*>(Vs + g * KP)[lane];
                oa.x = fmaf(pg, v4.x, oa.x);
                oa.y = fmaf(pg, v4.y, oa.y);
                oa.z = fmaf(pg, v4.z, oa.z);
                oa.w = fmaf(pg, v4.w, oa.w);
            }

            float* F = g_fused + base + (long)h * CW;
            if (br == 0) {
                reinterpret_cast<float4*>(F)[lane] = oa;
            } else {
                float4 pr = reinterpret_cast<const float4*>(F)[lane];
                oa.x += pr.x; oa.y += pr.y; oa.z += pr.z; oa.w += pr.w;
                reinterpret_cast<float4*>(F)[lane] = oa;
                lsum += oa.x + oa.y + oa.z + oa.w;
                lsq  += oa.x*oa.x + oa.y*oa.y + oa.z*oa.z + oa.w*oa.w;
            }
        }
    }

    // block-reduce BN partials (deterministic, no atomics)
    for (int o = 16; o; o >>= 1) {
        lsum += __shfl_xor_sync(0xffffffffu, lsum, o);
        lsq  += __shfl_xor_sync(0xffffffffu, lsq , o);
    }
    __syncthreads();
    if (lane == 0) { rbuf[warp] = lsum; rbuf[64 + warp] = lsq; }
    __syncthreads();
    if (t == 0) {
        float s = 0.f, q = 0.f;
        for (int w2 = 0; w2 < 16; w2++) { s += rbuf[w2]; q += rbuf[64 + w2]; }
        g_psum[bc] = s;
        g_psumsq[bc] = q;
    }
}

// ============================================================
// BN stats finalize: per-channel mean/var -> scale/shift
// ============================================================
__global__ void stats_kernel(const float* __restrict__ gamma, const float* __restrict__ beta)
{
    int c = threadIdx.x;
    if (c < CC) {
        double s = 0.0, q = 0.0;
        for (int b = 0; b < CB; b++) {
            s += (double)g_psum[b * CC + c];
            q += (double)g_psumsq[b * CC + c];
        }
        double nn = (double)CB * (double)CN;
        double mean = s / nn;
        double var = q / nn - mean * mean;
        float a = (float)((double)gamma[c] * rsqrt(var + 1e-5));
        g_scale[c] = a;
        g_shift[c] = beta[c] - (float)mean * a;
    }
}

// ============================================================
// Normalize + ReLU (float4)
// ============================================================
__global__ void norm_kernel(float* __restrict__ out)
{
    long i4 = (long)blockIdx.x * blockDim.x + threadIdx.x;
    if (i4 < (TOTE / 4)) {
        int c = (int)((i4 >> 12) & 63);  // (4*i4 / 16384) % 64
        float a = g_scale[c], sh = g_shift[c];
        float4 f = reinterpret_cast<const float4*>(g_fused)[i4];
        float4 r;
        r.x = fmaxf(0.f, fmaf(f.x, a, sh));
        r.y = fmaxf(0.f, fmaf(f.y, a, sh));
        r.z = fmaxf(0.f, fmaf(f.z, a, sh));
        r.w = fmaxf(0.f, fmaf(f.w, a, sh));
        reinterpret_cast<float4*>(out)[i4] = r;
    }
}

// ============================================================
// Launch
// ============================================================
#define ATTN_SMEM (2*128*KP*4 + 16*128*4)   // 143360 B
#define PROJ_SMEM (3*4096*4)                // 49152 B

extern "C" void kernel_launch(void* const* d_in, const int* in_sizes, int n_in,
                              void* d_out, int out_size)
{
    const float* x1    = (const float*)d_in[0];
    const float* x2    = (const float*)d_in[1];
    const float* rssi1 = (const float*)d_in[2];
    const float* rssi2 = (const float*)d_in[3];
    const float* qw    = (const float*)d_in[4];
    const float* qb    = (const float*)d_in[5];
    const float* kw    = (const float*)d_in[6];
    const float* kb    = (const float*)d_in[7];
    const float* vw    = (const float*)d_in[8];
    const float* vb    = (const float*)d_in[9];
    const float* gamma = (const float*)d_in[10];
    const float* beta  = (const float*)d_in[11];
    float* out = (float*)d_out;

    cudaFuncSetAttribute(proj_kernel, cudaFuncAttributeMaxDynamicSharedMemorySize, PROJ_SMEM);
    cudaFuncSetAttribute(attn_kernel, cudaFuncAttributeMaxDynamicSharedMemorySize, ATTN_SMEM);

    dim3 pg(CN / 256, CB);   // 64 x 16
    proj_kernel<<<pg, 256, PROJ_SMEM>>>(x1, rssi1, qw, qb, kw, kb, vw, vb, 0);
    proj_kernel<<<pg, 256, PROJ_SMEM>>>(x2, rssi2, qw, qb, kw, kb, vw, vb, 1);
    attn_kernel<<<CB * CC, 512, ATTN_SMEM>>>();
    stats_kernel<<<1, 64>>>(gamma, beta);
    norm_kernel<<<TOTE / 4 / 256, 256>>>(out);
}

// round 5
// speedup vs baseline: 1.6379x; 1.6379x over previous
#include <cuda_runtime.h>

// Problem constants
#define CB 16               // batch
#define CC 64               // channels
#define CH 128
#define CW 128
#define CN (CH*CW)          // 16384 spatial positions
#define PLANE ((long)CC*CN) // elems per batch = 1048576
#define TOTE 16777216       // total elems

// -------- scratch (device globals: allocation-guard-safe) --------
__device__ float g_q[2][TOTE];
__device__ float g_k[2][TOTE];
__device__ float g_v[2][TOTE];
__device__ float g_fused[TOTE];
__device__ float g_psum[CB*CC];
__device__ float g_psumsq[CB*CC];
__device__ float g_scale[CC];
__device__ float g_shift[CC];

// ============================================================
// Projection: out[b,o,n] = sum_c W[o,c]*in[b,c,n] + bias[o]
// One thread owns one spatial column n (64-ch column in registers).
// ============================================================
__device__ __forceinline__ void proj_one(const float* __restrict__ ws,
                                         const float* __restrict__ bias,
                                         const float col[64],
                                         float* __restrict__ out, long base)
{
#pragma unroll 2
    for (int og = 0; og < 64; og += 8) {
        float acc[8];
#pragma unroll
        for (int j = 0; j < 8; j++) acc[j] = __ldg(bias + og + j);
#pragma unroll
        for (int c4 = 0; c4 < 16; c4++) {
#pragma unroll
            for (int j = 0; j < 8; j++) {
                float4 w4 = *reinterpret_cast<const float4*>(ws + (og + j) * 64 + c4 * 4);
                acc[j] = fmaf(w4.x, col[c4*4+0], acc[j]);
                acc[j] = fmaf(w4.y, col[c4*4+1], acc[j]);
                acc[j] = fmaf(w4.z, col[c4*4+2], acc[j]);
                acc[j] = fmaf(w4.w, col[c4*4+3], acc[j]);
            }
        }
#pragma unroll
        for (int j = 0; j < 8; j++) out[base + (long)(og + j) * CN] = acc[j];
    }
}

__global__ void proj_kernel(const float* __restrict__ x, const float* __restrict__ rssi,
                            const float* __restrict__ qw, const float* __restrict__ qb,
                            const float* __restrict__ kw, const float* __restrict__ kb,
                            const float* __restrict__ vw, const float* __restrict__ vb,
                            int branch)
{
    extern __shared__ float sw[];           // 3 * 4096 floats = 48KB
    float* swq = sw;
    float* swk = sw + 4096;
    float* swv = sw + 8192;
    int t = threadIdx.x;
    for (int i = t; i < 4096; i += 256) { swq[i] = qw[i]; swk[i] = kw[i]; swv[i] = vw[i]; }
    __syncthreads();

    int b = blockIdx.y;
    int n = blockIdx.x * 256 + t;
    long base = (long)b * PLANE + n;

    float col[64];

    // Q from rssi
#pragma unroll
    for (int c = 0; c < 64; c++) col[c] = rssi[base + (long)c * CN];
    proj_one(swq, qb, col, g_q[branch], base);

    // K, V from x (load column once, use twice)
#pragma unroll
    for (int c = 0; c < 64; c++) col[c] = x[base + (long)c * CN];
    proj_one(swk, kb, col, g_k[branch], base);
    proj_one(swv, vb, col, g_v[branch], base);
}

// ============================================================
// Attention per (b,c): S = Q K^T * 1/sqrt(128), softmax rows, O = S V.
// 4-row register blocking: each K/V smem load feeds 16 FMAs.
// Branch 0 writes g_fused, branch 1 adds and collects BN partials.
// ============================================================
#define KP 132   // smem pitch in floats: 132/4=33 (odd) -> conflict-free LDS.128 rows

__global__ void attn_kernel()
{
    extern __shared__ float sm[];
    float* Ks   = sm;                    // 128*132
    float* Vs   = sm + 128 * KP;         // 128*132
    float* wbuf = sm + 2 * 128 * KP;     // 16 warps * 512 floats (q stage -> p transposed)

    int t = threadIdx.x;
    int lane = t & 31;
    int warp = t >> 5;
    int bc = blockIdx.x;                 // b*64 + c
    long base = (long)bc * CN;

    const float sc = 0.088388347648318447f;  // 1/sqrt(128)
    float lsum = 0.f, lsq = 0.f;

    float* wb = wbuf + warp * 512;

    for (int br = 0; br < 2; br++) {
        const float* Qp = g_q[br] + base;
        const float* Kp = g_k[br] + base;
        const float* Vp = g_v[br] + base;

        __syncthreads();   // protect smem reuse across branches
        for (int i = t; i < 128 * 32; i += 512) {
            int g = i >> 5, wv = i & 31;
            reinterpret_cast<float4*>(Ks + g * KP)[wv] =
                reinterpret_cast<const float4*>(Kp + g * CW)[wv];
            reinterpret_cast<float4*>(Vs + g * KP)[wv] =
                reinterpret_cast<const float4*>(Vp + g * CW)[wv];
        }
        __syncthreads();

        // each warp owns 8 rows, processed as 2 blocks of 4
#pragma unroll 1
        for (int blk = 0; blk < 2; blk++) {
            int h0 = warp * 8 + blk * 4;

            // stage 4 q rows: wb[r*128 + c]
            __syncwarp();
#pragma unroll
            for (int r = 0; r < 4; r++) {
                float4 qv = reinterpret_cast<const float4*>(Qp + (long)(h0 + r) * CW)[lane];
                reinterpret_cast<float4*>(wb + r * 128)[lane] = qv;
            }
            __syncwarp();

            // phase 1: scores acc[gq][r] for g = lane + 32*gq, rows h0..h0+3
            float acc[4][4];
#pragma unroll
            for (int gq = 0; gq < 4; gq++)
#pragma unroll
                for (int r = 0; r < 4; r++) acc[gq][r] = 0.f;

#pragma unroll 4
            for (int wv = 0; wv < 32; wv++) {
                float4 q0 = reinterpret_cast<const float4*>(wb      )[wv];
                float4 q1 = reinterpret_cast<const float4*>(wb + 128)[wv];
                float4 q2 = reinterpret_cast<const float4*>(wb + 256)[wv];
                float4 q3 = reinterpret_cast<const float4*>(wb + 384)[wv];
#pragma unroll
                for (int gq = 0; gq < 4; gq++) {
                    float4 k = reinterpret_cast<const float4*>(Ks + (lane + 32 * gq) * KP)[wv];
                    acc[gq][0] = fmaf(q0.x,k.x, fmaf(q0.y,k.y, fmaf(q0.z,k.z, fmaf(q0.w,k.w, acc[gq][0]))));
                    acc[gq][1] = fmaf(q1.x,k.x, fmaf(q1.y,k.y, fmaf(q1.z,k.z, fmaf(q1.w,k.w, acc[gq][1]))));
                    acc[gq][2] = fmaf(q2.x,k.x, fmaf(q2.y,k.y, fmaf(q2.z,k.z, fmaf(q2.w,k.w, acc[gq][2]))));
                    acc[gq][3] = fmaf(q3.x,k.x, fmaf(q3.y,k.y, fmaf(q3.z,k.z, fmaf(q3.w,k.w, acc[gq][3]))));
                }
            }

            // softmax per row (scale folded into exp)
            float m[4], s[4];
#pragma unroll
            for (int r = 0; r < 4; r++)
                m[r] = fmaxf(fmaxf(acc[0][r], acc[1][r]), fmaxf(acc[2][r], acc[3][r]));
#pragma unroll
            for (int o = 16; o; o >>= 1)
#pragma unroll
                for (int r = 0; r < 4; r++)
                    m[r] = fmaxf(m[r], __shfl_xor_sync(0xffffffffu, m[r], o));
#pragma unroll
            for (int gq = 0; gq < 4; gq++)
#pragma unroll
                for (int r = 0; r < 4; r++)
                    acc[gq][r] = __expf((acc[gq][r] - m[r]) * sc);
#pragma unroll
            for (int r = 0; r < 4; r++)
                s[r] = acc[0][r] + acc[1][r] + acc[2][r] + acc[3][r];
#pragma unroll
            for (int o = 16; o; o >>= 1)
#pragma unroll
                for (int r = 0; r < 4; r++)
                    s[r] += __shfl_xor_sync(0xffffffffu, s[r], o);
#pragma unroll
            for (int r = 0; r < 4; r++) s[r] = 1.f / s[r];

            // store p transposed: wb[g*4 + r] (contiguous float4 per g)
            __syncwarp();   // all lanes done reading q from wb
#pragma unroll
            for (int gq = 0; gq < 4; gq++) {
                float4 pv = make_float4(acc[gq][0]*s[0], acc[gq][1]*s[1],
                                        acc[gq][2]*s[2], acc[gq][3]*s[3]);
                reinterpret_cast<float4*>(wb)[lane + 32 * gq] = pv;
            }
            __syncwarp();

            // phase 2: O rows (lane owns 4 consecutive w); 2 LDS.128 : 16 FMA
            float4 oa[4];
#pragma unroll
            for (int r = 0; r < 4; r++) oa[r] = make_float4(0.f, 0.f, 0.f, 0.f);
#pragma unroll 4
            for (int g = 0; g < 128; g++) {
                float4 p4 = reinterpret_cast<const float4*>(wb)[g];       // broadcast
                float4 v4 = reinterpret_cast<const float4*>(Vs + g * KP)[lane];
                oa[0].x = fmaf(p4.x, v4.x, oa[0].x); oa[0].y = fmaf(p4.x, v4.y, oa[0].y);
                oa[0].z = fmaf(p4.x, v4.z, oa[0].z); oa[0].w = fmaf(p4.x, v4.w, oa[0].w);
                oa[1].x = fmaf(p4.y, v4.x, oa[1].x); oa[1].y = fmaf(p4.y, v4.y, oa[1].y);
                oa[1].z = fmaf(p4.y, v4.z, oa[1].z); oa[1].w = fmaf(p4.y, v4.w, oa[1].w);
                oa[2].x = fmaf(p4.z, v4.x, oa[2].x); oa[2].y = fmaf(p4.z, v4.y, oa[2].y);
                oa[2].z = fmaf(p4.z, v4.z, oa[2].z); oa[2].w = fmaf(p4.z, v4.w, oa[2].w);
                oa[3].x = fmaf(p4.w, v4.x, oa[3].x); oa[3].y = fmaf(p4.w, v4.y, oa[3].y);
                oa[3].z = fmaf(p4.w, v4.z, oa[3].z); oa[3].w = fmaf(p4.w, v4.w, oa[3].w);
            }

#pragma unroll
            for (int r = 0; r < 4; r++) {
                float* F = g_fused + base + (long)(h0 + r) * CW;
                float4 o4 = oa[r];
                if (br == 0) {
                    reinterpret_cast<float4*>(F)[lane] = o4;
                } else {
                    float4 pr = reinterpret_cast<const float4*>(F)[lane];
                    o4.x += pr.x; o4.y += pr.y; o4.z += pr.z; o4.w += pr.w;
                    reinterpret_cast<float4*>(F)[lane] = o4;
                    lsum += o4.x + o4.y + o4.z + o4.w;
                    lsq  += o4.x*o4.x + o4.y*o4.y + o4.z*o4.z + o4.w*o4.w;
                }
            }
        }
    }

    // block-reduce BN partials (deterministic, no atomics)
#pragma unroll
    for (int o = 16; o; o >>= 1) {
        lsum += __shfl_xor_sync(0xffffffffu, lsum, o);
        lsq  += __shfl_xor_sync(0xffffffffu, lsq , o);
    }
    __syncthreads();
    if (lane == 0) { wbuf[warp] = lsum; wbuf[64 + warp] = lsq; }
    __syncthreads();
    if (t == 0) {
        float s = 0.f, q = 0.f;
        for (int w2 = 0; w2 < 16; w2++) { s += wbuf[w2]; q += wbuf[64 + w2]; }
        g_psum[bc] = s;
        g_psumsq[bc] = q;
    }
}

// ============================================================
// BN stats finalize: per-channel mean/var -> scale/shift
// ============================================================
__global__ void stats_kernel(const float* __restrict__ gamma, const float* __restrict__ beta)
{
    int c = threadIdx.x;
    if (c < CC) {
        double s = 0.0, q = 0.0;
        for (int b = 0; b < CB; b++) {
            s += (double)g_psum[b * CC + c];
            q += (double)g_psumsq[b * CC + c];
        }
        double nn = (double)CB * (double)CN;
        double mean = s / nn;
        double var = q / nn - mean * mean;
        float a = (float)((double)gamma[c] * rsqrt(var + 1e-5));
        g_scale[c] = a;
        g_shift[c] = beta[c] - (float)mean * a;
    }
}

// ============================================================
// Normalize + ReLU (float4)
// ============================================================
__global__ void norm_kernel(float* __restrict__ out)
{
    long i4 = (long)blockIdx.x * blockDim.x + threadIdx.x;
    if (i4 < (TOTE / 4)) {
        int c = (int)((i4 >> 12) & 63);
        float a = g_scale[c], sh = g_shift[c];
        float4 f = reinterpret_cast<const float4*>(g_fused)[i4];
        float4 r;
        r.x = fmaxf(0.f, fmaf(f.x, a, sh));
        r.y = fmaxf(0.f, fmaf(f.y, a, sh));
        r.z = fmaxf(0.f, fmaf(f.z, a, sh));
        r.w = fmaxf(0.f, fmaf(f.w, a, sh));
        reinterpret_cast<float4*>(out)[i4] = r;
    }
}

// ============================================================
// Launch
// ============================================================
#define ATTN_SMEM (2*128*KP*4 + 16*512*4)   // 135168 + 32768 = 167936 B
#define PROJ_SMEM (3*4096*4)                // 49152 B

extern "C" void kernel_launch(void* const* d_in, const int* in_sizes, int n_in,
                              void* d_out, int out_size)
{
    const float* x1    = (const float*)d_in[0];
    const float* x2    = (const float*)d_in[1];
    const float* rssi1 = (const float*)d_in[2];
    const float* rssi2 = (const float*)d_in[3];
    const float* qw    = (const float*)d_in[4];
    const float* qb    = (const float*)d_in[5];
    const float* kw    = (const float*)d_in[6];
    const float* kb    = (const float*)d_in[7];
    const float* vw    = (const float*)d_in[8];
    const float* vb    = (const float*)d_in[9];
    const float* gamma = (const float*)d_in[10];
    const float* beta  = (const float*)d_in[11];
    float* out = (float*)d_out;

    cudaFuncSetAttribute(proj_kernel, cudaFuncAttributeMaxDynamicSharedMemorySize, PROJ_SMEM);
    cudaFuncSetAttribute(attn_kernel, cudaFuncAttributeMaxDynamicSharedMemorySize, ATTN_SMEM);

    dim3 pg(CN / 256, CB);   // 64 x 16
    proj_kernel<<<pg, 256, PROJ_SMEM>>>(x1, rssi1, qw, qb, kw, kb, vw, vb, 0);
    proj_kernel<<<pg, 256, PROJ_SMEM>>>(x2, rssi2, qw, qb, kw, kb, vw, vb, 1);
    attn_kernel<<<CB * CC, 512, ATTN_SMEM>>>();
    stats_kernel<<<1, 64>>>(gamma, beta);
    norm_kernel<<<TOTE / 4 / 256, 256>>>(out);
}